// round 5
// baseline (speedup 1.0000x reference)
#include <cuda_runtime.h>
#include <cuda_bf16.h>
#include <cuda_fp8.h>
#include <stdint.h>

#define NR 8192
#define DD 512
#define BM 128
#define BKB 64               // k bytes (fp8 elems) per stage
#define NKT (DD / BKB)       // 8 k-tiles
#define NBLK (NR / BM)       // 64
#define NTRI (NBLK * (NBLK + 1) / 2)   // 2080 tiles
#define GRID 304             // persistent CTAs (152 SMs x occ 2)
#define STAGES 4
#define SSTB 80                        // smem row stride bytes (conflict-free ldmatrix)
#define TILE_SMEM (BM * SSTB)          // 10240
#define STAGE_SMEM (2 * TILE_SMEM)     // 20480
#define EPI_SMEM (STAGES * STAGE_SMEM) // epilogue buffers after stages
#define SMEM_TOTAL (EPI_SMEM + 3072)   // +rowbuf(1KB)+colbuf(2KB)

// ---- device scratch ----
__device__ __align__(16) uint8_t g_ne[NR * DD];
__device__ float g_pos[NR];
__device__ float g_Spart[NBLK][NR];
__device__ float g_blocksum[32];
__device__ int g_cnt;   // zero-init; self-resets each run

// ============================================================
// Kernel A: normalize -> e4m3 (float4 loads, packed stores)
// ============================================================
__global__ void norm_kernel(const float* __restrict__ emb, const float* __restrict__ tgt) {
    int row = blockIdx.x;
    int t = threadIdx.x; // 128
    float4 a = reinterpret_cast<const float4*>(emb + (size_t)row * DD)[t];
    float4 b = reinterpret_cast<const float4*>(tgt + (size_t)row * DD)[t];

    float ee = a.x*a.x + a.y*a.y + a.z*a.z + a.w*a.w;
    float tt = b.x*b.x + b.y*b.y + b.z*b.z + b.w*b.w;
    float et = a.x*b.x + a.y*b.y + a.z*b.z + a.w*b.w;
#pragma unroll
    for (int o = 16; o > 0; o >>= 1) {
        ee += __shfl_xor_sync(0xFFFFFFFFu, ee, o);
        tt += __shfl_xor_sync(0xFFFFFFFFu, tt, o);
        et += __shfl_xor_sync(0xFFFFFFFFu, et, o);
    }
    __shared__ float sred[3][4];
    int w = t >> 5, l = t & 31;
    if (l == 0) { sred[0][w] = ee; sred[1][w] = tt; sred[2][w] = et; }
    __syncthreads();
    ee = sred[0][0] + sred[0][1] + sred[0][2] + sred[0][3];
    tt = sred[1][0] + sred[1][1] + sred[1][2] + sred[1][3];
    et = sred[2][0] + sred[2][1] + sred[2][2] + sred[2][3];

    float inv_e = rsqrtf(ee);
    if (t == 0) g_pos[row] = et * inv_e * rsqrtf(tt);

    uint32_t p =
        (uint32_t)__nv_cvt_float_to_fp8(a.x * inv_e, __NV_SATFINITE, __NV_E4M3)
      | ((uint32_t)__nv_cvt_float_to_fp8(a.y * inv_e, __NV_SATFINITE, __NV_E4M3) << 8)
      | ((uint32_t)__nv_cvt_float_to_fp8(a.z * inv_e, __NV_SATFINITE, __NV_E4M3) << 16)
      | ((uint32_t)__nv_cvt_float_to_fp8(a.w * inv_e, __NV_SATFINITE, __NV_E4M3) << 24);
    reinterpret_cast<uint32_t*>(g_ne)[(size_t)row * (DD / 4) + t] = p;
}

// ============================================================
// MMA / cp.async helpers
// ============================================================
__device__ __forceinline__ void ldsm_x4(uint32_t& r0, uint32_t& r1, uint32_t& r2, uint32_t& r3,
                                        uint32_t addr) {
    asm volatile("ldmatrix.sync.aligned.m8n8.x4.shared.b16 {%0,%1,%2,%3}, [%4];"
                 : "=r"(r0), "=r"(r1), "=r"(r2), "=r"(r3) : "r"(addr));
}
__device__ __forceinline__ void mma_fp8(float c[4], const uint32_t a[4], uint32_t b0, uint32_t b1) {
    asm volatile(
        "mma.sync.aligned.m16n8k32.row.col.f32.e4m3.e4m3.f32 "
        "{%0,%1,%2,%3}, {%4,%5,%6,%7}, {%8,%9}, {%0,%1,%2,%3};"
        : "+f"(c[0]), "+f"(c[1]), "+f"(c[2]), "+f"(c[3])
        : "r"(a[0]), "r"(a[1]), "r"(a[2]), "r"(a[3]), "r"(b0), "r"(b1));
}
__device__ __forceinline__ void cp16(uint32_t dst, const void* src) {
    asm volatile("cp.async.cg.shared.global [%0], [%1], 16;" :: "r"(dst), "l"(src));
}
__device__ __forceinline__ void cp_commit() {
    asm volatile("cp.async.commit_group;" ::: "memory");
}
template <int N>
__device__ __forceinline__ void cp_wait() {
    asm volatile("cp.async.wait_group %0;" :: "n"(N) : "memory");
}

__device__ __forceinline__ void decode_tri(int t, int& bi, int& bj) {
#define TRI_S(b) ((b) * 64 - ((b) * ((b) - 1)) / 2)
    int b = (int)(64.5f - sqrtf(64.5f * 64.5f - 2.0f * (float)t));
    if (b < 0) b = 0;
    if (b > 63) b = 63;
    while (b > 0 && TRI_S(b) > t) b--;
    while (b < 63 && TRI_S(b + 1) <= t) b++;
    bi = b;
    bj = b + (t - TRI_S(b));
}

// ============================================================
// Kernel B: persistent upper-triangle fp8 GEMM + exp(2x) row/col sums
// ============================================================
__global__ void __launch_bounds__(256, 2) gemm_lse_kernel() {
    extern __shared__ char smem[];
    const uint32_t sb = (uint32_t)__cvta_generic_to_shared(smem);

    const int tid = threadIdx.x;
    const int lane = tid & 31;
    const int wid = tid >> 5;
    const int warp_m = wid >> 1;
    const int warp_n = wid & 1;

    // cp.async coords
    const int r0c = tid >> 2;
    const int r1c = (tid + 256) >> 2;
    const int kc0 = (tid & 3) * 16;

    // ldmatrix per-lane addressing
    const int lrow = lane & 15;
    const int lkb  = (lane >> 4) * 16;
    const uint32_t aoff0 = (uint32_t)((warp_m * 32 + lrow) * SSTB + lkb);
    const uint32_t aoff1 = aoff0 + 16 * SSTB;
    uint32_t boff[4];
#pragma unroll
    for (int nj = 0; nj < 4; nj++)
        boff[nj] = (uint32_t)((warp_n * 64 + nj * 16 + lrow) * SSTB + lkb) + TILE_SMEM;

    float* rowbuf = (float*)(smem + EPI_SMEM);          // [2][128]
    float* colbuf = (float*)(smem + EPI_SMEM + 1024);   // [4][128]

    int t = blockIdx.x;
    int bi, bj;
    decode_tri(t, bi, bj);
    const uint8_t* gA = g_ne + (size_t)bi * BM * DD;
    const uint8_t* gB = g_ne + (size_t)bj * BM * DD;

    // prologue: chunks 0..2 of first tile
#pragma unroll
    for (int p = 0; p < STAGES - 1; p++) {
        uint32_t base = sb + p * STAGE_SMEM;
        cp16(base + r0c * SSTB + kc0, gA + (size_t)r0c * DD + p * BKB + kc0);
        cp16(base + r1c * SSTB + kc0, gA + (size_t)r1c * DD + p * BKB + kc0);
        cp16(base + TILE_SMEM + r0c * SSTB + kc0, gB + (size_t)r0c * DD + p * BKB + kc0);
        cp16(base + TILE_SMEM + r1c * SSTB + kc0, gB + (size_t)r1c * DD + p * BKB + kc0);
        cp_commit();
    }

    while (true) {
        // next-tile pointers (loads for it overlap this tile's last k-iters)
        int tn = t + GRID;
        bool has_next = (tn < NTRI);
        int bin = 0, bjn = 0;
        const uint8_t *gAn = gA, *gBn = gB;
        if (has_next) {
            decode_tri(tn, bin, bjn);
            gAn = g_ne + (size_t)bin * BM * DD;
            gBn = g_ne + (size_t)bjn * BM * DD;
        }

        float acc[2][8][4];
#pragma unroll
        for (int mi = 0; mi < 2; mi++)
#pragma unroll
            for (int ni = 0; ni < 8; ni++)
#pragma unroll
                for (int k = 0; k < 4; k++) acc[mi][ni][k] = 0.f;

#pragma unroll 2
        for (int kt = 0; kt < NKT; kt++) {
            cp_wait<STAGES - 2>();
            __syncthreads();

            int kl = kt + STAGES - 1;
            if (kl < NKT) {
                uint32_t base = sb + (kl & (STAGES - 1)) * STAGE_SMEM;
                cp16(base + r0c * SSTB + kc0, gA + (size_t)r0c * DD + kl * BKB + kc0);
                cp16(base + r1c * SSTB + kc0, gA + (size_t)r1c * DD + kl * BKB + kc0);
                cp16(base + TILE_SMEM + r0c * SSTB + kc0, gB + (size_t)r0c * DD + kl * BKB + kc0);
                cp16(base + TILE_SMEM + r1c * SSTB + kc0, gB + (size_t)r1c * DD + kl * BKB + kc0);
            } else if (has_next) {
                int kn = kl - NKT;   // 0..2, stage index continues mod 4
                uint32_t base = sb + (kl & (STAGES - 1)) * STAGE_SMEM;
                cp16(base + r0c * SSTB + kc0, gAn + (size_t)r0c * DD + kn * BKB + kc0);
                cp16(base + r1c * SSTB + kc0, gAn + (size_t)r1c * DD + kn * BKB + kc0);
                cp16(base + TILE_SMEM + r0c * SSTB + kc0, gBn + (size_t)r0c * DD + kn * BKB + kc0);
                cp16(base + TILE_SMEM + r1c * SSTB + kc0, gBn + (size_t)r1c * DD + kn * BKB + kc0);
            }
            cp_commit();

            uint32_t base = sb + (kt & (STAGES - 1)) * STAGE_SMEM;
#pragma unroll
            for (int ks = 0; ks < 2; ks++) {
                uint32_t a[2][4], b[4][4];
                ldsm_x4(a[0][0], a[0][1], a[0][2], a[0][3], base + aoff0 + ks * 32);
                ldsm_x4(a[1][0], a[1][1], a[1][2], a[1][3], base + aoff1 + ks * 32);
#pragma unroll
                for (int nj = 0; nj < 4; nj++)
                    ldsm_x4(b[nj][0], b[nj][1], b[nj][2], b[nj][3], base + boff[nj] + ks * 32);
#pragma unroll
                for (int mi = 0; mi < 2; mi++)
#pragma unroll
                    for (int ni = 0; ni < 8; ni++)
                        mma_fp8(acc[mi][ni], a[mi], b[ni >> 1][ni & 1], b[ni >> 1][(ni & 1) + 2]);
            }
        }

        // ---- epilogue (dedicated smem; pipeline for next tile stays in flight) ----
        const bool diag = (bi == bj);
#pragma unroll
        for (int mi = 0; mi < 2; mi++)
#pragma unroll
            for (int ni = 0; ni < 8; ni++)
#pragma unroll
                for (int k = 0; k < 4; k++) {
                    float x = acc[mi][ni][k];
                    acc[mi][ni][k] = __expf(x + x);
                }

#pragma unroll
        for (int mi = 0; mi < 2; mi++) {
            float r0 = 0.f, r1 = 0.f;
#pragma unroll
            for (int ni = 0; ni < 8; ni++) {
                r0 += acc[mi][ni][0] + acc[mi][ni][1];
                r1 += acc[mi][ni][2] + acc[mi][ni][3];
            }
            r0 += __shfl_xor_sync(0xFFFFFFFFu, r0, 1);
            r0 += __shfl_xor_sync(0xFFFFFFFFu, r0, 2);
            r1 += __shfl_xor_sync(0xFFFFFFFFu, r1, 1);
            r1 += __shfl_xor_sync(0xFFFFFFFFu, r1, 2);
            if ((lane & 3) == 0) {
                int rr = warp_m * 32 + mi * 16 + (lane >> 2);
                rowbuf[warp_n * 128 + rr] = r0;
                rowbuf[warp_n * 128 + rr + 8] = r1;
            }
        }
        if (!diag) {
#pragma unroll
            for (int ni = 0; ni < 8; ni++) {
                float ce = acc[0][ni][0] + acc[0][ni][2] + acc[1][ni][0] + acc[1][ni][2];
                float co = acc[0][ni][1] + acc[0][ni][3] + acc[1][ni][1] + acc[1][ni][3];
                ce += __shfl_xor_sync(0xFFFFFFFFu, ce, 4);
                ce += __shfl_xor_sync(0xFFFFFFFFu, ce, 8);
                ce += __shfl_xor_sync(0xFFFFFFFFu, ce, 16);
                co += __shfl_xor_sync(0xFFFFFFFFu, co, 4);
                co += __shfl_xor_sync(0xFFFFFFFFu, co, 8);
                co += __shfl_xor_sync(0xFFFFFFFFu, co, 16);
                if (lane < 4) {
                    int cc = warp_n * 64 + ni * 8 + lane * 2;
                    colbuf[warp_m * 128 + cc] = ce;
                    colbuf[warp_m * 128 + cc + 1] = co;
                }
            }
        }
        __syncthreads();
        if (tid < 128) {
            g_Spart[bj][bi * BM + tid] = rowbuf[tid] + rowbuf[128 + tid];
            if (!diag)
                g_Spart[bi][bj * BM + tid] =
                    colbuf[tid] + colbuf[128 + tid] + colbuf[256 + tid] + colbuf[384 + tid];
        }

        if (!has_next) break;
        t = tn; bi = bin; bj = bjn; gA = gAn; gB = gBn;
    }
}

// ============================================================
// Kernel C: per-row combine + hierarchical final (single kernel)
// ============================================================
__global__ void reduce_kernel(float* __restrict__ out) {
    int row = blockIdx.x * 256 + threadIdx.x;
    float s = 0.f;
#pragma unroll 8
    for (int p = 0; p < NBLK; p++) s += g_Spart[p][row];
    float v = logf(s) - 2.f * g_pos[row];
#pragma unroll
    for (int o = 16; o > 0; o >>= 1) v += __shfl_xor_sync(0xFFFFFFFFu, v, o);
    __shared__ float sw[8];
    __shared__ int slast;
    int t = threadIdx.x;
    if ((t & 31) == 0) sw[t >> 5] = v;
    __syncthreads();
    if (t == 0) {
        float tot = 0.f;
#pragma unroll
        for (int w = 0; w < 8; w++) tot += sw[w];
        g_blocksum[blockIdx.x] = tot;
        __threadfence();
        int prev = atomicAdd(&g_cnt, 1);
        slast = (prev == 31) ? 1 : 0;
    }
    __syncthreads();
    if (slast && t < 32) {
        __threadfence();
        float x = g_blocksum[t];
#pragma unroll
        for (int o = 16; o > 0; o >>= 1) x += __shfl_xor_sync(0xFFFFFFFFu, x, o);
        if (t == 0) {
            out[0] = x * (1.0f / (2.0f * NR));
            g_cnt = 0;   // reset for next graph replay
        }
    }
}

// ============================================================
extern "C" void kernel_launch(void* const* d_in, const int* in_sizes, int n_in,
                              void* d_out, int out_size) {
    const float* emb = (const float*)d_in[0];
    const float* tgt = (const float*)d_in[1];
    float* out = (float*)d_out;

    cudaFuncSetAttribute(gemm_lse_kernel, cudaFuncAttributeMaxDynamicSharedMemorySize, SMEM_TOTAL);

    norm_kernel<<<NR, 128>>>(emb, tgt);
    gemm_lse_kernel<<<GRID, 256, SMEM_TOTAL>>>();
    reduce_kernel<<<32, 256>>>(out);
}

// round 6
// speedup vs baseline: 1.1403x; 1.1403x over previous
#include <cuda_runtime.h>
#include <cuda_bf16.h>
#include <cuda_fp8.h>
#include <stdint.h>

#define NR 8192
#define DD 512
#define BM 128
#define BKB 64               // k bytes (fp8 elems) per stage
#define NKT (DD / BKB)       // 8 k-tiles
#define NBLK (NR / BM)       // 64
#define NTRI (NBLK * (NBLK + 1) / 2)   // 2080 tiles
#define STAGES 4
#define SSTB 80                        // smem row stride bytes (conflict-free ldmatrix)
#define TILE_SMEM (BM * SSTB)          // 10240
#define STAGE_SMEM (2 * TILE_SMEM)     // 20480
#define SMEM_TOTAL (STAGES * STAGE_SMEM)  // 81920

// ---- device scratch ----
__device__ __align__(16) uint8_t g_ne[NR * DD];
__device__ float g_pos[NR];
__device__ float g_Spart[NBLK][NR];
__device__ float g_blocksum[32];
__device__ int g_cnt;   // zero-init; self-resets each run

// ============================================================
// Kernel A: normalize -> e4m3 (float4 loads, packed stores)
// ============================================================
__global__ void norm_kernel(const float* __restrict__ emb, const float* __restrict__ tgt) {
    int row = blockIdx.x;
    int t = threadIdx.x; // 128
    float4 a = reinterpret_cast<const float4*>(emb + (size_t)row * DD)[t];
    float4 b = reinterpret_cast<const float4*>(tgt + (size_t)row * DD)[t];

    float ee = a.x*a.x + a.y*a.y + a.z*a.z + a.w*a.w;
    float tt = b.x*b.x + b.y*b.y + b.z*b.z + b.w*b.w;
    float et = a.x*b.x + a.y*b.y + a.z*b.z + a.w*b.w;
#pragma unroll
    for (int o = 16; o > 0; o >>= 1) {
        ee += __shfl_xor_sync(0xFFFFFFFFu, ee, o);
        tt += __shfl_xor_sync(0xFFFFFFFFu, tt, o);
        et += __shfl_xor_sync(0xFFFFFFFFu, et, o);
    }
    __shared__ float sred[3][4];
    int w = t >> 5, l = t & 31;
    if (l == 0) { sred[0][w] = ee; sred[1][w] = tt; sred[2][w] = et; }
    __syncthreads();
    ee = sred[0][0] + sred[0][1] + sred[0][2] + sred[0][3];
    tt = sred[1][0] + sred[1][1] + sred[1][2] + sred[1][3];
    et = sred[2][0] + sred[2][1] + sred[2][2] + sred[2][3];

    float inv_e = rsqrtf(ee);
    if (t == 0) g_pos[row] = et * inv_e * rsqrtf(tt);

    uint32_t p =
        (uint32_t)__nv_cvt_float_to_fp8(a.x * inv_e, __NV_SATFINITE, __NV_E4M3)
      | ((uint32_t)__nv_cvt_float_to_fp8(a.y * inv_e, __NV_SATFINITE, __NV_E4M3) << 8)
      | ((uint32_t)__nv_cvt_float_to_fp8(a.z * inv_e, __NV_SATFINITE, __NV_E4M3) << 16)
      | ((uint32_t)__nv_cvt_float_to_fp8(a.w * inv_e, __NV_SATFINITE, __NV_E4M3) << 24);
    reinterpret_cast<uint32_t*>(g_ne)[(size_t)row * (DD / 4) + t] = p;
}

// ============================================================
// MMA / cp.async helpers
// ============================================================
__device__ __forceinline__ void ldsm_x4(uint32_t& r0, uint32_t& r1, uint32_t& r2, uint32_t& r3,
                                        uint32_t addr) {
    asm volatile("ldmatrix.sync.aligned.m8n8.x4.shared.b16 {%0,%1,%2,%3}, [%4];"
                 : "=r"(r0), "=r"(r1), "=r"(r2), "=r"(r3) : "r"(addr));
}
__device__ __forceinline__ void mma_fp8(float c[4], const uint32_t a[4], uint32_t b0, uint32_t b1) {
    asm volatile(
        "mma.sync.aligned.m16n8k32.row.col.f32.e4m3.e4m3.f32 "
        "{%0,%1,%2,%3}, {%4,%5,%6,%7}, {%8,%9}, {%0,%1,%2,%3};"
        : "+f"(c[0]), "+f"(c[1]), "+f"(c[2]), "+f"(c[3])
        : "r"(a[0]), "r"(a[1]), "r"(a[2]), "r"(a[3]), "r"(b0), "r"(b1));
}
__device__ __forceinline__ void cp16(uint32_t dst, const void* src) {
    asm volatile("cp.async.cg.shared.global [%0], [%1], 16;" :: "r"(dst), "l"(src));
}
__device__ __forceinline__ void cp_commit() {
    asm volatile("cp.async.commit_group;" ::: "memory");
}
template <int N>
__device__ __forceinline__ void cp_wait() {
    asm volatile("cp.async.wait_group %0;" :: "n"(N) : "memory");
}

// ============================================================
// Kernel B: upper-triangle fp8 GEMM + exp(2x) row/col sums
//   128x128 tile, 256 thr, occ 2, 4-stage cp.async (R4 structure)
// ============================================================
__global__ void __launch_bounds__(256, 2) gemm_lse_kernel() {
    extern __shared__ char smem[];
    const uint32_t sb = (uint32_t)__cvta_generic_to_shared(smem);

    const int tid = threadIdx.x;
    const int lane = tid & 31;
    const int wid = tid >> 5;
    const int warp_m = wid >> 1;
    const int warp_n = wid & 1;

    // ---- decode upper-triangle tile index -> (bi, bj), bi <= bj ----
    int t = blockIdx.x;
    int bi = (int)(64.5f - sqrtf(64.5f * 64.5f - 2.0f * (float)t));
    if (bi < 0) bi = 0;
    if (bi > 63) bi = 63;
#define TRI_S(b) ((b) * 64 - ((b) * ((b) - 1)) / 2)
    while (bi > 0 && TRI_S(bi) > t) bi--;
    while (bi < 63 && TRI_S(bi + 1) <= t) bi++;
    const int bj = bi + (t - TRI_S(bi));
    const bool diag = (bi == bj);

    const uint8_t* gA = g_ne + (size_t)bi * BM * DD;
    const uint8_t* gB = g_ne + (size_t)bj * BM * DD;

    // cp.async coords: tile = 128 rows x 64B = 512 x 16B chunks, 2/thread/operand
    const int r0c = tid >> 2;
    const int r1c = (tid + 256) >> 2;
    const int kc0 = (tid & 3) * 16;

    // ldmatrix per-lane addressing (fp8 m16n8k32 fragment order)
    const int lrow = lane & 15;
    const int lkb  = (lane >> 4) * 16;
    const uint32_t aoff0 = (uint32_t)((warp_m * 32 + lrow) * SSTB + lkb);
    const uint32_t aoff1 = aoff0 + 16 * SSTB;
    uint32_t boff[4];
#pragma unroll
    for (int nj = 0; nj < 4; nj++)
        boff[nj] = (uint32_t)((warp_n * 64 + nj * 16 + lrow) * SSTB + lkb) + TILE_SMEM;

    float acc[2][8][4];
#pragma unroll
    for (int mi = 0; mi < 2; mi++)
#pragma unroll
        for (int ni = 0; ni < 8; ni++)
#pragma unroll
            for (int k = 0; k < 4; k++) acc[mi][ni][k] = 0.f;

    // ---- prologue: fill STAGES-1 stages ----
#pragma unroll
    for (int p = 0; p < STAGES - 1; p++) {
        uint32_t base = sb + p * STAGE_SMEM;
        cp16(base + r0c * SSTB + kc0, gA + (size_t)r0c * DD + p * BKB + kc0);
        cp16(base + r1c * SSTB + kc0, gA + (size_t)r1c * DD + p * BKB + kc0);
        cp16(base + TILE_SMEM + r0c * SSTB + kc0, gB + (size_t)r0c * DD + p * BKB + kc0);
        cp16(base + TILE_SMEM + r1c * SSTB + kc0, gB + (size_t)r1c * DD + p * BKB + kc0);
        cp_commit();
    }

    for (int kt = 0; kt < NKT; kt++) {
        cp_wait<STAGES - 2>();
        __syncthreads();

        uint32_t base = sb + (kt & (STAGES - 1)) * STAGE_SMEM;

        // critical-path ldsm for ks=0 FIRST (LSU services these before the cp quads)
        uint32_t a[2][4], b[4][4];
        ldsm_x4(a[0][0], a[0][1], a[0][2], a[0][3], base + aoff0);
        ldsm_x4(a[1][0], a[1][1], a[1][2], a[1][3], base + aoff1);
#pragma unroll
        for (int nj = 0; nj < 4; nj++)
            ldsm_x4(b[nj][0], b[nj][1], b[nj][2], b[nj][3], base + boff[nj]);

        // now issue next-stage async loads (off critical path)
        int kl = kt + STAGES - 1;
        if (kl < NKT) {
            uint32_t lb = sb + (kl & (STAGES - 1)) * STAGE_SMEM;
            cp16(lb + r0c * SSTB + kc0, gA + (size_t)r0c * DD + kl * BKB + kc0);
            cp16(lb + r1c * SSTB + kc0, gA + (size_t)r1c * DD + kl * BKB + kc0);
            cp16(lb + TILE_SMEM + r0c * SSTB + kc0, gB + (size_t)r0c * DD + kl * BKB + kc0);
            cp16(lb + TILE_SMEM + r1c * SSTB + kc0, gB + (size_t)r1c * DD + kl * BKB + kc0);
        }
        cp_commit();

        // mma ks=0
#pragma unroll
        for (int mi = 0; mi < 2; mi++)
#pragma unroll
            for (int ni = 0; ni < 8; ni++)
                mma_fp8(acc[mi][ni], a[mi], b[ni >> 1][ni & 1], b[ni >> 1][(ni & 1) + 2]);

        // ks=1: ldsm then mma
        ldsm_x4(a[0][0], a[0][1], a[0][2], a[0][3], base + aoff0 + 32);
        ldsm_x4(a[1][0], a[1][1], a[1][2], a[1][3], base + aoff1 + 32);
#pragma unroll
        for (int nj = 0; nj < 4; nj++)
            ldsm_x4(b[nj][0], b[nj][1], b[nj][2], b[nj][3], base + boff[nj] + 32);
#pragma unroll
        for (int mi = 0; mi < 2; mi++)
#pragma unroll
            for (int ni = 0; ni < 8; ni++)
                mma_fp8(acc[mi][ni], a[mi], b[ni >> 1][ni & 1], b[ni >> 1][(ni & 1) + 2]);
    }

    // ---- epilogue: exp(2x); row sums always, col sums if off-diagonal ----
#pragma unroll
    for (int mi = 0; mi < 2; mi++)
#pragma unroll
        for (int ni = 0; ni < 8; ni++)
#pragma unroll
            for (int k = 0; k < 4; k++) {
                float x = acc[mi][ni][k];
                acc[mi][ni][k] = __expf(x + x);
            }

    float* rowbuf = (float*)smem;               // [2][128]
    float* colbuf = (float*)(smem + 1024);      // [4][128]
    __syncthreads();  // all compute done before aliasing smem

#pragma unroll
    for (int mi = 0; mi < 2; mi++) {
        float r0 = 0.f, r1 = 0.f;
#pragma unroll
        for (int ni = 0; ni < 8; ni++) {
            r0 += acc[mi][ni][0] + acc[mi][ni][1];
            r1 += acc[mi][ni][2] + acc[mi][ni][3];
        }
        r0 += __shfl_xor_sync(0xFFFFFFFFu, r0, 1);
        r0 += __shfl_xor_sync(0xFFFFFFFFu, r0, 2);
        r1 += __shfl_xor_sync(0xFFFFFFFFu, r1, 1);
        r1 += __shfl_xor_sync(0xFFFFFFFFu, r1, 2);
        if ((lane & 3) == 0) {
            int rr = warp_m * 32 + mi * 16 + (lane >> 2);
            rowbuf[warp_n * 128 + rr] = r0;
            rowbuf[warp_n * 128 + rr + 8] = r1;
        }
    }

    if (!diag) {
#pragma unroll
        for (int ni = 0; ni < 8; ni++) {
            float ce = acc[0][ni][0] + acc[0][ni][2] + acc[1][ni][0] + acc[1][ni][2];
            float co = acc[0][ni][1] + acc[0][ni][3] + acc[1][ni][1] + acc[1][ni][3];
            ce += __shfl_xor_sync(0xFFFFFFFFu, ce, 4);
            ce += __shfl_xor_sync(0xFFFFFFFFu, ce, 8);
            ce += __shfl_xor_sync(0xFFFFFFFFu, ce, 16);
            co += __shfl_xor_sync(0xFFFFFFFFu, co, 4);
            co += __shfl_xor_sync(0xFFFFFFFFu, co, 8);
            co += __shfl_xor_sync(0xFFFFFFFFu, co, 16);
            if (lane < 4) {
                int cc = warp_n * 64 + ni * 8 + lane * 2;
                colbuf[warp_m * 128 + cc] = ce;
                colbuf[warp_m * 128 + cc + 1] = co;
            }
        }
    }
    __syncthreads();

    if (tid < 128) {
        g_Spart[bj][bi * BM + tid] = rowbuf[tid] + rowbuf[128 + tid];
        if (!diag)
            g_Spart[bi][bj * BM + tid] =
                colbuf[tid] + colbuf[128 + tid] + colbuf[256 + tid] + colbuf[384 + tid];
    }
}

// ============================================================
// Kernel C: per-row combine + hierarchical final (single kernel)
// ============================================================
__global__ void reduce_kernel(float* __restrict__ out) {
    int row = blockIdx.x * 256 + threadIdx.x;
    float s = 0.f;
#pragma unroll 8
    for (int p = 0; p < NBLK; p++) s += g_Spart[p][row];
    float v = logf(s) - 2.f * g_pos[row];
#pragma unroll
    for (int o = 16; o > 0; o >>= 1) v += __shfl_xor_sync(0xFFFFFFFFu, v, o);
    __shared__ float sw[8];
    __shared__ int slast;
    int t = threadIdx.x;
    if ((t & 31) == 0) sw[t >> 5] = v;
    __syncthreads();
    if (t == 0) {
        float tot = 0.f;
#pragma unroll
        for (int w = 0; w < 8; w++) tot += sw[w];
        g_blocksum[blockIdx.x] = tot;
        __threadfence();
        int prev = atomicAdd(&g_cnt, 1);
        slast = (prev == 31) ? 1 : 0;
    }
    __syncthreads();
    if (slast && t < 32) {
        __threadfence();
        float x = g_blocksum[t];
#pragma unroll
        for (int o = 16; o > 0; o >>= 1) x += __shfl_xor_sync(0xFFFFFFFFu, x, o);
        if (t == 0) {
            out[0] = x * (1.0f / (2.0f * NR));
            g_cnt = 0;   // reset for next graph replay
        }
    }
}

// ============================================================
extern "C" void kernel_launch(void* const* d_in, const int* in_sizes, int n_in,
                              void* d_out, int out_size) {
    const float* emb = (const float*)d_in[0];
    const float* tgt = (const float*)d_in[1];
    float* out = (float*)d_out;

    cudaFuncSetAttribute(gemm_lse_kernel, cudaFuncAttributeMaxDynamicSharedMemorySize, SMEM_TOTAL);

    norm_kernel<<<NR, 128>>>(emb, tgt);
    gemm_lse_kernel<<<NTRI, 256, SMEM_TOTAL>>>();
    reduce_kernel<<<32, 256>>>(out);
}

// round 7
// speedup vs baseline: 1.1548x; 1.0127x over previous
#include <cuda_runtime.h>
#include <cuda_bf16.h>
#include <cuda_fp8.h>
#include <stdint.h>

#define NR 8192
#define DD 512
#define BM 128
#define BKB 64               // k bytes (fp8 elems) per stage
#define NKT (DD / BKB)       // 8 k-tiles
#define NBLK (NR / BM)       // 64
#define NTRI (NBLK * (NBLK + 1) / 2)   // 2080 tiles
#define STAGES 4
#define SSTB 80                        // smem row stride bytes (conflict-free ldmatrix)
#define TILE_SMEM (BM * SSTB)          // 10240
#define STAGE_SMEM (2 * TILE_SMEM)     // 20480
#define SMEM_TOTAL (STAGES * STAGE_SMEM)  // 81920

// ---- device scratch ----
__device__ __align__(16) uint8_t g_ne[NR * DD];
__device__ float g_pos[NR];
__device__ float g_Spart[NBLK][NR];
__device__ float g_blocksum[32];
__device__ int g_cnt;   // zero-init; self-resets each run

// ============================================================
// Kernel A: normalize -> e4m3 (warp per row, shfl-only)
// ============================================================
__global__ void __launch_bounds__(256) norm_kernel(const float* __restrict__ emb,
                                                   const float* __restrict__ tgt) {
    int row = blockIdx.x * 8 + (threadIdx.x >> 5);
    int l = threadIdx.x & 31;
    const float4* e  = reinterpret_cast<const float4*>(emb + (size_t)row * DD);
    const float4* tg = reinterpret_cast<const float4*>(tgt + (size_t)row * DD);

    float4 a[4], b[4];
    float ee = 0.f, tt = 0.f, et = 0.f;
#pragma unroll
    for (int j = 0; j < 4; j++) {
        a[j] = e[l + 32 * j];
        b[j] = tg[l + 32 * j];
        ee += a[j].x*a[j].x + a[j].y*a[j].y + a[j].z*a[j].z + a[j].w*a[j].w;
        tt += b[j].x*b[j].x + b[j].y*b[j].y + b[j].z*b[j].z + b[j].w*b[j].w;
        et += a[j].x*b[j].x + a[j].y*b[j].y + a[j].z*b[j].z + a[j].w*b[j].w;
    }
#pragma unroll
    for (int o = 16; o > 0; o >>= 1) {
        ee += __shfl_xor_sync(0xFFFFFFFFu, ee, o);
        tt += __shfl_xor_sync(0xFFFFFFFFu, tt, o);
        et += __shfl_xor_sync(0xFFFFFFFFu, et, o);
    }
    float inv_e = rsqrtf(ee);
    if (l == 0) g_pos[row] = et * inv_e * rsqrtf(tt);

#pragma unroll
    for (int j = 0; j < 4; j++) {
        uint32_t p =
            (uint32_t)__nv_cvt_float_to_fp8(a[j].x * inv_e, __NV_SATFINITE, __NV_E4M3)
          | ((uint32_t)__nv_cvt_float_to_fp8(a[j].y * inv_e, __NV_SATFINITE, __NV_E4M3) << 8)
          | ((uint32_t)__nv_cvt_float_to_fp8(a[j].z * inv_e, __NV_SATFINITE, __NV_E4M3) << 16)
          | ((uint32_t)__nv_cvt_float_to_fp8(a[j].w * inv_e, __NV_SATFINITE, __NV_E4M3) << 24);
        reinterpret_cast<uint32_t*>(g_ne)[(size_t)row * (DD / 4) + l + 32 * j] = p;
    }
}

// ============================================================
// MMA / cp.async helpers
// ============================================================
__device__ __forceinline__ void ldsm_x4(uint32_t& r0, uint32_t& r1, uint32_t& r2, uint32_t& r3,
                                        uint32_t addr) {
    asm volatile("ldmatrix.sync.aligned.m8n8.x4.shared.b16 {%0,%1,%2,%3}, [%4];"
                 : "=r"(r0), "=r"(r1), "=r"(r2), "=r"(r3) : "r"(addr));
}
__device__ __forceinline__ void mma_fp8(float c[4], const uint32_t a[4], uint32_t b0, uint32_t b1) {
    asm volatile(
        "mma.sync.aligned.m16n8k32.row.col.f32.e4m3.e4m3.f32 "
        "{%0,%1,%2,%3}, {%4,%5,%6,%7}, {%8,%9}, {%0,%1,%2,%3};"
        : "+f"(c[0]), "+f"(c[1]), "+f"(c[2]), "+f"(c[3])
        : "r"(a[0]), "r"(a[1]), "r"(a[2]), "r"(a[3]), "r"(b0), "r"(b1));
}
__device__ __forceinline__ void cp16(uint32_t dst, const void* src) {
    asm volatile("cp.async.cg.shared.global [%0], [%1], 16;" :: "r"(dst), "l"(src));
}
__device__ __forceinline__ void cp_commit() {
    asm volatile("cp.async.commit_group;" ::: "memory");
}
template <int N>
__device__ __forceinline__ void cp_wait() {
    asm volatile("cp.async.wait_group %0;" :: "n"(N) : "memory");
}

// ============================================================
// Kernel B: upper-triangle fp8 GEMM + exp(2x) row/col sums
// ============================================================
__global__ void __launch_bounds__(256, 2) gemm_lse_kernel() {
    extern __shared__ char smem[];
    const uint32_t sb = (uint32_t)__cvta_generic_to_shared(smem);

    const int tid = threadIdx.x;
    const int lane = tid & 31;
    const int wid = tid >> 5;
    const int warp_m = wid >> 1;
    const int warp_n = wid & 1;
    const int ksel = wid & 1;      // ks processing order: even warps 0,1; odd warps 1,0

    // ---- decode upper-triangle tile index -> (bi, bj), bi <= bj ----
    int t = blockIdx.x;
    int bi = (int)(64.5f - sqrtf(64.5f * 64.5f - 2.0f * (float)t));
    if (bi < 0) bi = 0;
    if (bi > 63) bi = 63;
#define TRI_S(b) ((b) * 64 - ((b) * ((b) - 1)) / 2)
    while (bi > 0 && TRI_S(bi) > t) bi--;
    while (bi < 63 && TRI_S(bi + 1) <= t) bi++;
    const int bj = bi + (t - TRI_S(bi));
    const bool diag = (bi == bj);

    const uint8_t* gA = g_ne + (size_t)bi * BM * DD;
    const uint8_t* gB = g_ne + (size_t)bj * BM * DD;

    // cp.async coords
    const int r0c = tid >> 2;
    const int r1c = (tid + 256) >> 2;
    const int kc0 = (tid & 3) * 16;

    // ldmatrix per-lane addressing
    const int lrow = lane & 15;
    const int lkb  = (lane >> 4) * 16;
    const uint32_t aoff0 = (uint32_t)((warp_m * 32 + lrow) * SSTB + lkb);
    const uint32_t aoff1 = aoff0 + 16 * SSTB;
    uint32_t boff[4];
#pragma unroll
    for (int nj = 0; nj < 4; nj++)
        boff[nj] = (uint32_t)((warp_n * 64 + nj * 16 + lrow) * SSTB + lkb) + TILE_SMEM;

    float acc[2][8][4];
#pragma unroll
    for (int mi = 0; mi < 2; mi++)
#pragma unroll
        for (int ni = 0; ni < 8; ni++)
#pragma unroll
            for (int k = 0; k < 4; k++) acc[mi][ni][k] = 0.f;

    // ---- prologue: fill STAGES-1 stages ----
#pragma unroll
    for (int p = 0; p < STAGES - 1; p++) {
        uint32_t base = sb + p * STAGE_SMEM;
        cp16(base + r0c * SSTB + kc0, gA + (size_t)r0c * DD + p * BKB + kc0);
        cp16(base + r1c * SSTB + kc0, gA + (size_t)r1c * DD + p * BKB + kc0);
        cp16(base + TILE_SMEM + r0c * SSTB + kc0, gB + (size_t)r0c * DD + p * BKB + kc0);
        cp16(base + TILE_SMEM + r1c * SSTB + kc0, gB + (size_t)r1c * DD + p * BKB + kc0);
        cp_commit();
    }

#pragma unroll
    for (int kt = 0; kt < NKT; kt++) {
        cp_wait<STAGES - 2>();
        __syncthreads();

        uint32_t base = sb + (kt & (STAGES - 1)) * STAGE_SMEM;
        const uint32_t o0 = (uint32_t)ksel * 32;          // first ks half (warp-staggered)
        const uint32_t o1 = o0 ^ 32;                      // second ks half

        // first-half ldsm (critical path)
        uint32_t a[2][4], b[4][4];
        ldsm_x4(a[0][0], a[0][1], a[0][2], a[0][3], base + aoff0 + o0);
        ldsm_x4(a[1][0], a[1][1], a[1][2], a[1][3], base + aoff1 + o0);
#pragma unroll
        for (int nj = 0; nj < 4; nj++)
            ldsm_x4(b[nj][0], b[nj][1], b[nj][2], b[nj][3], base + boff[nj] + o0);

        // next-stage async loads (off critical path)
        if (kt + STAGES - 1 < NKT) {
            const int kl = kt + STAGES - 1;
            uint32_t lb = sb + (kl & (STAGES - 1)) * STAGE_SMEM;
            cp16(lb + r0c * SSTB + kc0, gA + (size_t)r0c * DD + kl * BKB + kc0);
            cp16(lb + r1c * SSTB + kc0, gA + (size_t)r1c * DD + kl * BKB + kc0);
            cp16(lb + TILE_SMEM + r0c * SSTB + kc0, gB + (size_t)r0c * DD + kl * BKB + kc0);
            cp16(lb + TILE_SMEM + r1c * SSTB + kc0, gB + (size_t)r1c * DD + kl * BKB + kc0);
        }
        cp_commit();

#pragma unroll
        for (int mi = 0; mi < 2; mi++)
#pragma unroll
            for (int ni = 0; ni < 8; ni++)
                mma_fp8(acc[mi][ni], a[mi], b[ni >> 1][ni & 1], b[ni >> 1][(ni & 1) + 2]);

        // second half
        ldsm_x4(a[0][0], a[0][1], a[0][2], a[0][3], base + aoff0 + o1);
        ldsm_x4(a[1][0], a[1][1], a[1][2], a[1][3], base + aoff1 + o1);
#pragma unroll
        for (int nj = 0; nj < 4; nj++)
            ldsm_x4(b[nj][0], b[nj][1], b[nj][2], b[nj][3], base + boff[nj] + o1);
#pragma unroll
        for (int mi = 0; mi < 2; mi++)
#pragma unroll
            for (int ni = 0; ni < 8; ni++)
                mma_fp8(acc[mi][ni], a[mi], b[ni >> 1][ni & 1], b[ni >> 1][(ni & 1) + 2]);
    }

    // ---- epilogue: exp(2x); row sums always, col sums if off-diagonal ----
#pragma unroll
    for (int mi = 0; mi < 2; mi++)
#pragma unroll
        for (int ni = 0; ni < 8; ni++)
#pragma unroll
            for (int k = 0; k < 4; k++) {
                float x = acc[mi][ni][k];
                acc[mi][ni][k] = __expf(x + x);
            }

    float* rowbuf = (float*)smem;               // [2][128]
    float* colbuf = (float*)(smem + 1024);      // [4][128]
    __syncthreads();  // all compute done before aliasing smem

#pragma unroll
    for (int mi = 0; mi < 2; mi++) {
        float r0 = 0.f, r1 = 0.f;
#pragma unroll
        for (int ni = 0; ni < 8; ni++) {
            r0 += acc[mi][ni][0] + acc[mi][ni][1];
            r1 += acc[mi][ni][2] + acc[mi][ni][3];
        }
        r0 += __shfl_xor_sync(0xFFFFFFFFu, r0, 1);
        r0 += __shfl_xor_sync(0xFFFFFFFFu, r0, 2);
        r1 += __shfl_xor_sync(0xFFFFFFFFu, r1, 1);
        r1 += __shfl_xor_sync(0xFFFFFFFFu, r1, 2);
        if ((lane & 3) == 0) {
            int rr = warp_m * 32 + mi * 16 + (lane >> 2);
            rowbuf[warp_n * 128 + rr] = r0;
            rowbuf[warp_n * 128 + rr + 8] = r1;
        }
    }

    if (!diag) {
#pragma unroll
        for (int ni = 0; ni < 8; ni++) {
            float ce = acc[0][ni][0] + acc[0][ni][2] + acc[1][ni][0] + acc[1][ni][2];
            float co = acc[0][ni][1] + acc[0][ni][3] + acc[1][ni][1] + acc[1][ni][3];
            ce += __shfl_xor_sync(0xFFFFFFFFu, ce, 4);
            ce += __shfl_xor_sync(0xFFFFFFFFu, ce, 8);
            ce += __shfl_xor_sync(0xFFFFFFFFu, ce, 16);
            co += __shfl_xor_sync(0xFFFFFFFFu, co, 4);
            co += __shfl_xor_sync(0xFFFFFFFFu, co, 8);
            co += __shfl_xor_sync(0xFFFFFFFFu, co, 16);
            if (lane < 4) {
                int cc = warp_n * 64 + ni * 8 + lane * 2;
                colbuf[warp_m * 128 + cc] = ce;
                colbuf[warp_m * 128 + cc + 1] = co;
            }
        }
    }
    __syncthreads();

    if (tid < 128) {
        g_Spart[bj][bi * BM + tid] = rowbuf[tid] + rowbuf[128 + tid];
        if (!diag)
            g_Spart[bi][bj * BM + tid] =
                colbuf[tid] + colbuf[128 + tid] + colbuf[256 + tid] + colbuf[384 + tid];
    }
}

// ============================================================
// Kernel C: per-row combine + hierarchical final (single kernel)
// ============================================================
__global__ void reduce_kernel(float* __restrict__ out) {
    int row = blockIdx.x * 256 + threadIdx.x;
    float s = 0.f;
#pragma unroll 8
    for (int p = 0; p < NBLK; p++) s += g_Spart[p][row];
    float v = logf(s) - 2.f * g_pos[row];
#pragma unroll
    for (int o = 16; o > 0; o >>= 1) v += __shfl_xor_sync(0xFFFFFFFFu, v, o);
    __shared__ float sw[8];
    __shared__ int slast;
    int t = threadIdx.x;
    if ((t & 31) == 0) sw[t >> 5] = v;
    __syncthreads();
    if (t == 0) {
        float tot = 0.f;
#pragma unroll
        for (int w = 0; w < 8; w++) tot += sw[w];
        g_blocksum[blockIdx.x] = tot;
        __threadfence();
        int prev = atomicAdd(&g_cnt, 1);
        slast = (prev == 31) ? 1 : 0;
    }
    __syncthreads();
    if (slast && t < 32) {
        __threadfence();
        float x = g_blocksum[t];
#pragma unroll
        for (int o = 16; o > 0; o >>= 1) x += __shfl_xor_sync(0xFFFFFFFFu, x, o);
        if (t == 0) {
            out[0] = x * (1.0f / (2.0f * NR));
            g_cnt = 0;   // reset for next graph replay
        }
    }
}

// ============================================================
extern "C" void kernel_launch(void* const* d_in, const int* in_sizes, int n_in,
                              void* d_out, int out_size) {
    const float* emb = (const float*)d_in[0];
    const float* tgt = (const float*)d_in[1];
    float* out = (float*)d_out;

    cudaFuncSetAttribute(gemm_lse_kernel, cudaFuncAttributeMaxDynamicSharedMemorySize, SMEM_TOTAL);

    norm_kernel<<<NR / 8, 256>>>(emb, tgt);
    gemm_lse_kernel<<<NTRI, 256, SMEM_TOTAL>>>();
    reduce_kernel<<<32, 256>>>(out);
}